// round 3
// baseline (speedup 1.0000x reference)
#include <cuda_runtime.h>
#include <cuda_bf16.h>

// out[n] = prod_f sigmoid(10*(x[n,f]*w[f]+b[f]))^(1/2)
//        = rsqrt( prod_f (1 + exp2( (x*w+b) * (-10*log2 e) )) )
// Half-warp (16 lanes x float4) covers one 64-float row; warp covers 2 rows
// per LDG.128. Unroll x4: each warp-iter front-batches 4 independent LDG.128
// (rows 8q..8q+7 = 2 KB) for MLP=4, then runs 4 interleaved MUFU/SHFL chains.

#ifndef GRID_BLOCKS
#define GRID_BLOCKS 1184   // 148 SMs * 8 CTAs
#endif

__global__ __launch_bounds__(256)
void one_to_one_prod_kernel(const float* __restrict__ x,
                            const float* __restrict__ w,
                            const float* __restrict__ b,
                            float* __restrict__ out,
                            long long n_rows)
{
    const int lane  = threadIdx.x & 31;
    const int half  = lane >> 4;       // which row of a pair
    const int hlane = lane & 15;       // lane within half-warp

    const float NEG10_LOG2E = -14.4269504088896340736f; // -10 * log2(e)
    float4 w4 = reinterpret_cast<const float4*>(w)[hlane];
    float4 b4 = reinterpret_cast<const float4*>(b)[hlane];
    w4.x *= NEG10_LOG2E; w4.y *= NEG10_LOG2E; w4.z *= NEG10_LOG2E; w4.w *= NEG10_LOG2E;
    b4.x *= NEG10_LOG2E; b4.y *= NEG10_LOG2E; b4.z *= NEG10_LOG2E; b4.w *= NEG10_LOG2E;

    const long long warp_id = (long long)blockIdx.x * (blockDim.x >> 5) + (threadIdx.x >> 5);
    const long long n_warps = (long long)gridDim.x * (blockDim.x >> 5);
    const long long n_octs  = n_rows >> 3;      // 8 rows per warp-iter

    for (long long q = warp_id; q < n_octs; q += n_warps) {
        const long long row0 = 8 * q + half;    // this lane: rows row0, +2, +4, +6
        const float* base = x + row0 * 64;

        // Front-batch 4 independent LDG.128 (MLP=4 per warp)
        const float4 v0 = __ldcs(reinterpret_cast<const float4*>(base)         + hlane);
        const float4 v1 = __ldcs(reinterpret_cast<const float4*>(base + 128)   + hlane);
        const float4 v2 = __ldcs(reinterpret_cast<const float4*>(base + 256)   + hlane);
        const float4 v3 = __ldcs(reinterpret_cast<const float4*>(base + 384)   + hlane);

        // 4 independent MUFU chains
        float a0 = exp2f(fmaf(v0.x, w4.x, b4.x));
        float a1 = exp2f(fmaf(v0.y, w4.y, b4.y));
        float a2 = exp2f(fmaf(v0.z, w4.z, b4.z));
        float a3 = exp2f(fmaf(v0.w, w4.w, b4.w));

        float c0 = exp2f(fmaf(v1.x, w4.x, b4.x));
        float c1 = exp2f(fmaf(v1.y, w4.y, b4.y));
        float c2 = exp2f(fmaf(v1.z, w4.z, b4.z));
        float c3 = exp2f(fmaf(v1.w, w4.w, b4.w));

        float d0 = exp2f(fmaf(v2.x, w4.x, b4.x));
        float d1 = exp2f(fmaf(v2.y, w4.y, b4.y));
        float d2 = exp2f(fmaf(v2.z, w4.z, b4.z));
        float d3 = exp2f(fmaf(v2.w, w4.w, b4.w));

        float g0 = exp2f(fmaf(v3.x, w4.x, b4.x));
        float g1 = exp2f(fmaf(v3.y, w4.y, b4.y));
        float g2 = exp2f(fmaf(v3.z, w4.z, b4.z));
        float g3 = exp2f(fmaf(v3.w, w4.w, b4.w));

        float f0 = rsqrtf((1.0f + a0) * (1.0f + a1) * (1.0f + a2) * (1.0f + a3));
        float f1 = rsqrtf((1.0f + c0) * (1.0f + c1) * (1.0f + c2) * (1.0f + c3));
        float f2 = rsqrtf((1.0f + d0) * (1.0f + d1) * (1.0f + d2) * (1.0f + d3));
        float f3 = rsqrtf((1.0f + g0) * (1.0f + g1) * (1.0f + g2) * (1.0f + g3));

        // 4 interleaved multiply-reductions across each 16-lane half-warp
        #pragma unroll
        for (int off = 8; off > 0; off >>= 1) {
            f0 *= __shfl_xor_sync(0xFFFFFFFFu, f0, off, 16);
            f1 *= __shfl_xor_sync(0xFFFFFFFFu, f1, off, 16);
            f2 *= __shfl_xor_sync(0xFFFFFFFFu, f2, off, 16);
            f3 *= __shfl_xor_sync(0xFFFFFFFFu, f3, off, 16);
        }

        if (hlane == 0) {
            // lanes 0/16 write rows {row0, +2, +4, +6} — 8 adjacent floats = 32B
            __stcs(out + row0,     f0);
            __stcs(out + row0 + 2, f1);
            __stcs(out + row0 + 4, f2);
            __stcs(out + row0 + 6, f3);
        }
    }

    // Tail (n_rows not divisible by 8): leftover rows pair-wise.
    const long long tail_start = n_octs * 8;
    if (tail_start < n_rows) {
        const long long n_pairs_tail = (n_rows - tail_start) >> 1;
        for (long long t = warp_id; t < n_pairs_tail; t += n_warps) {
            const long long row = tail_start + 2 * t + half;
            const float4 v = __ldcs(reinterpret_cast<const float4*>(x + row * 64) + hlane);
            float e0 = exp2f(fmaf(v.x, w4.x, b4.x));
            float e1 = exp2f(fmaf(v.y, w4.y, b4.y));
            float e2 = exp2f(fmaf(v.z, w4.z, b4.z));
            float e3 = exp2f(fmaf(v.w, w4.w, b4.w));
            float f = rsqrtf((1.0f + e0) * (1.0f + e1) * (1.0f + e2) * (1.0f + e3));
            #pragma unroll
            for (int off = 8; off > 0; off >>= 1)
                f *= __shfl_xor_sync(0xFFFFFFFFu, f, off, 16);
            if (hlane == 0) out[row] = f;
        }
        if ((n_rows - tail_start) & 1) {
            if (warp_id == 0) {
                const long long row = n_rows - 1;
                const float4 v = __ldcs(reinterpret_cast<const float4*>(x + row * 64) + hlane);
                float e0 = exp2f(fmaf(v.x, w4.x, b4.x));
                float e1 = exp2f(fmaf(v.y, w4.y, b4.y));
                float e2 = exp2f(fmaf(v.z, w4.z, b4.z));
                float e3 = exp2f(fmaf(v.w, w4.w, b4.w));
                float f = rsqrtf((1.0f + e0) * (1.0f + e1) * (1.0f + e2) * (1.0f + e3));
                #pragma unroll
                for (int off = 8; off > 0; off >>= 1)
                    f *= __shfl_xor_sync(0xFFFFFFFFu, f, off, 32);
                if (lane == 0) out[row] = f;
            }
        }
    }
}

extern "C" void kernel_launch(void* const* d_in, const int* in_sizes, int n_in,
                              void* d_out, int out_size)
{
    const float* x = (const float*)d_in[0];   // [N, 64]
    const float* w = (const float*)d_in[1];   // [64]
    const float* b = (const float*)d_in[2];   // [64]
    float* out = (float*)d_out;               // [N]

    const long long n_rows = (long long)in_sizes[0] / 64;

    one_to_one_prod_kernel<<<GRID_BLOCKS, 256>>>(x, w, b, out, n_rows);
}

// round 4
// speedup vs baseline: 1.1268x; 1.1268x over previous
#include <cuda_runtime.h>
#include <cuda_bf16.h>

// out[n] = prod_f sigmoid(10*(x[n,f]*w[f]+b[f]))^(1/2)
//        = rsqrt( prod_f (1 + exp2( (x*w+b) * (-10*log2 e) )) )
// Half-warp (16 lanes x float4) covers one 64-float row; warp covers 2 rows
// per LDG.128. Unroll x4 (8 rows / 2KB per warp-iter, MLP=4), with ALL
// indexing in 32-bit so the kernel fits in 32 regs -> 8 CTAs/SM resident,
// grid 1184 = exactly one resident wave of persistent CTAs.

#define GRID_BLOCKS 1184   // 148 SMs * 8 CTAs

__global__ __launch_bounds__(256, 8)
void one_to_one_prod_kernel(const float* __restrict__ x,
                            const float* __restrict__ w,
                            const float* __restrict__ b,
                            float* __restrict__ out,
                            unsigned n_rows)
{
    const unsigned lane  = threadIdx.x & 31u;
    const unsigned half  = lane >> 4;       // which row of a pair
    const unsigned hlane = lane & 15u;      // lane within half-warp

    const float NEG10_LOG2E = -14.4269504088896340736f; // -10 * log2(e)
    float4 w4 = reinterpret_cast<const float4*>(w)[hlane];
    float4 b4 = reinterpret_cast<const float4*>(b)[hlane];
    w4.x *= NEG10_LOG2E; w4.y *= NEG10_LOG2E; w4.z *= NEG10_LOG2E; w4.w *= NEG10_LOG2E;
    b4.x *= NEG10_LOG2E; b4.y *= NEG10_LOG2E; b4.z *= NEG10_LOG2E; b4.w *= NEG10_LOG2E;

    const unsigned warp_id = blockIdx.x * (blockDim.x >> 5) + (threadIdx.x >> 5);
    const unsigned n_warps = gridDim.x * (blockDim.x >> 5);
    const unsigned n_octs  = n_rows >> 3;       // 8 rows per warp-iter

    // x viewed as float4; row r starts at float4 index r*16. Max index:
    // 2^21 rows * 16 = 2^25 -- fits 32-bit with room.
    const float4* __restrict__ xv = reinterpret_cast<const float4*>(x);

    for (unsigned q = warp_id; q < n_octs; q += n_warps) {
        const unsigned row0 = 8u * q + half;        // this lane: rows row0,+2,+4,+6
        const unsigned i0 = row0 * 16u + hlane;     // float4 index

        // Front-batch 4 independent LDG.128 (MLP=4 per warp)
        const float4 v0 = __ldcs(xv + i0);
        const float4 v1 = __ldcs(xv + i0 + 32u);    // +2 rows
        const float4 v2 = __ldcs(xv + i0 + 64u);    // +4 rows
        const float4 v3 = __ldcs(xv + i0 + 96u);    // +6 rows

        // 4 independent MUFU chains
        float a0 = exp2f(fmaf(v0.x, w4.x, b4.x));
        float a1 = exp2f(fmaf(v0.y, w4.y, b4.y));
        float a2 = exp2f(fmaf(v0.z, w4.z, b4.z));
        float a3 = exp2f(fmaf(v0.w, w4.w, b4.w));

        float c0 = exp2f(fmaf(v1.x, w4.x, b4.x));
        float c1 = exp2f(fmaf(v1.y, w4.y, b4.y));
        float c2 = exp2f(fmaf(v1.z, w4.z, b4.z));
        float c3 = exp2f(fmaf(v1.w, w4.w, b4.w));

        float d0 = exp2f(fmaf(v2.x, w4.x, b4.x));
        float d1 = exp2f(fmaf(v2.y, w4.y, b4.y));
        float d2 = exp2f(fmaf(v2.z, w4.z, b4.z));
        float d3 = exp2f(fmaf(v2.w, w4.w, b4.w));

        float g0 = exp2f(fmaf(v3.x, w4.x, b4.x));
        float g1 = exp2f(fmaf(v3.y, w4.y, b4.y));
        float g2 = exp2f(fmaf(v3.z, w4.z, b4.z));
        float g3 = exp2f(fmaf(v3.w, w4.w, b4.w));

        float f0 = rsqrtf((1.0f + a0) * (1.0f + a1) * (1.0f + a2) * (1.0f + a3));
        float f1 = rsqrtf((1.0f + c0) * (1.0f + c1) * (1.0f + c2) * (1.0f + c3));
        float f2 = rsqrtf((1.0f + d0) * (1.0f + d1) * (1.0f + d2) * (1.0f + d3));
        float f3 = rsqrtf((1.0f + g0) * (1.0f + g1) * (1.0f + g2) * (1.0f + g3));

        // 4 interleaved multiply-reductions across each 16-lane half-warp
        #pragma unroll
        for (int off = 8; off > 0; off >>= 1) {
            f0 *= __shfl_xor_sync(0xFFFFFFFFu, f0, off, 16);
            f1 *= __shfl_xor_sync(0xFFFFFFFFu, f1, off, 16);
            f2 *= __shfl_xor_sync(0xFFFFFFFFu, f2, off, 16);
            f3 *= __shfl_xor_sync(0xFFFFFFFFu, f3, off, 16);
        }

        if (hlane == 0u) {
            // lanes 0/16 write rows {row0,+2,+4,+6} — 8 adjacent floats = 32B
            __stcs(out + row0,      f0);
            __stcs(out + row0 + 2u, f1);
            __stcs(out + row0 + 4u, f2);
            __stcs(out + row0 + 6u, f3);
        }
    }

    // Tail (n_rows not divisible by 8): leftover rows pair-wise.
    const unsigned tail_start = n_octs * 8u;
    if (tail_start < n_rows) {
        const unsigned n_pairs_tail = (n_rows - tail_start) >> 1;
        for (unsigned t = warp_id; t < n_pairs_tail; t += n_warps) {
            const unsigned row = tail_start + 2u * t + half;
            const float4 v = __ldcs(xv + row * 16u + hlane);
            float e0 = exp2f(fmaf(v.x, w4.x, b4.x));
            float e1 = exp2f(fmaf(v.y, w4.y, b4.y));
            float e2 = exp2f(fmaf(v.z, w4.z, b4.z));
            float e3 = exp2f(fmaf(v.w, w4.w, b4.w));
            float f = rsqrtf((1.0f + e0) * (1.0f + e1) * (1.0f + e2) * (1.0f + e3));
            #pragma unroll
            for (int off = 8; off > 0; off >>= 1)
                f *= __shfl_xor_sync(0xFFFFFFFFu, f, off, 16);
            if (hlane == 0u) out[row] = f;
        }
        if ((n_rows - tail_start) & 1u) {
            if (warp_id == 0u) {
                const unsigned row = n_rows - 1u;
                const float4 v = __ldcs(xv + row * 16u + hlane);
                float e0 = exp2f(fmaf(v.x, w4.x, b4.x));
                float e1 = exp2f(fmaf(v.y, w4.y, b4.y));
                float e2 = exp2f(fmaf(v.z, w4.z, b4.z));
                float e3 = exp2f(fmaf(v.w, w4.w, b4.w));
                float f = rsqrtf((1.0f + e0) * (1.0f + e1) * (1.0f + e2) * (1.0f + e3));
                #pragma unroll
                for (int off = 8; off > 0; off >>= 1)
                    f *= __shfl_xor_sync(0xFFFFFFFFu, f, off, 32);
                if (lane == 0u) out[row] = f;
            }
        }
    }
}

extern "C" void kernel_launch(void* const* d_in, const int* in_sizes, int n_in,
                              void* d_out, int out_size)
{
    const float* x = (const float*)d_in[0];   // [N, 64]
    const float* w = (const float*)d_in[1];   // [64]
    const float* b = (const float*)d_in[2];   // [64]
    float* out = (float*)d_out;               // [N]

    const unsigned n_rows = (unsigned)((long long)in_sizes[0] / 64);

    one_to_one_prod_kernel<<<GRID_BLOCKS, 256>>>(x, w, b, out, n_rows);
}

// round 5
// speedup vs baseline: 1.1779x; 1.0454x over previous
#include <cuda_runtime.h>
#include <cuda_bf16.h>

// out[n] = prod_f sigmoid(10*(x[n,f]*w[f]+b[f]))^(1/2)
//        = rsqrt( prod_f (1 + exp2( (x*w+b) * (-10*log2 e) )) )
// Half-warp (16 lanes x float4) covers one 64-float row; warp covers 2 rows
// per LDG.128. Unroll x4 (8 rows / 2KB per warp-iter), 4 LDG.128 genuinely
// front-batched: 128-thread blocks with a 51-reg budget (launch_bounds 128,10)
// so ptxas keeps all 16 data regs + 8 const regs live -> true MLP=4.
// Grid = 148 SMs * 10 CTAs = exactly one resident wave of persistent CTAs.

#define GRID_BLOCKS 1480   // 148 SMs * 10 CTAs of 128 threads
#define BLOCK_THREADS 128

__global__ __launch_bounds__(BLOCK_THREADS, 10)
void one_to_one_prod_kernel(const float* __restrict__ x,
                            const float* __restrict__ w,
                            const float* __restrict__ b,
                            float* __restrict__ out,
                            unsigned n_rows)
{
    const unsigned lane  = threadIdx.x & 31u;
    const unsigned half  = lane >> 4;       // which row of a pair
    const unsigned hlane = lane & 15u;      // lane within half-warp

    const float NEG10_LOG2E = -14.4269504088896340736f; // -10 * log2(e)
    float4 w4 = reinterpret_cast<const float4*>(w)[hlane];
    float4 b4 = reinterpret_cast<const float4*>(b)[hlane];
    w4.x *= NEG10_LOG2E; w4.y *= NEG10_LOG2E; w4.z *= NEG10_LOG2E; w4.w *= NEG10_LOG2E;
    b4.x *= NEG10_LOG2E; b4.y *= NEG10_LOG2E; b4.z *= NEG10_LOG2E; b4.w *= NEG10_LOG2E;

    const unsigned warp_id = blockIdx.x * (blockDim.x >> 5) + (threadIdx.x >> 5);
    const unsigned n_warps = gridDim.x * (blockDim.x >> 5);
    const unsigned n_octs  = n_rows >> 3;       // 8 rows per warp-iter

    // x viewed as float4; row r starts at float4 index r*16.
    // Max index 2^21 * 16 = 2^25 -- fits 32-bit.
    const float4* __restrict__ xv = reinterpret_cast<const float4*>(x);

    for (unsigned q = warp_id; q < n_octs; q += n_warps) {
        const unsigned row0 = 8u * q + half;        // this lane: rows row0,+2,+4,+6
        const unsigned i0 = row0 * 16u + hlane;     // float4 index

        // Front-batch 4 independent LDG.128 (true MLP=4 with the 51-reg budget)
        const float4 v0 = __ldcs(xv + i0);
        const float4 v1 = __ldcs(xv + i0 + 32u);    // +2 rows
        const float4 v2 = __ldcs(xv + i0 + 64u);    // +4 rows
        const float4 v3 = __ldcs(xv + i0 + 96u);    // +6 rows

        // 4 independent MUFU chains
        float a0 = exp2f(fmaf(v0.x, w4.x, b4.x));
        float a1 = exp2f(fmaf(v0.y, w4.y, b4.y));
        float a2 = exp2f(fmaf(v0.z, w4.z, b4.z));
        float a3 = exp2f(fmaf(v0.w, w4.w, b4.w));

        float c0 = exp2f(fmaf(v1.x, w4.x, b4.x));
        float c1 = exp2f(fmaf(v1.y, w4.y, b4.y));
        float c2 = exp2f(fmaf(v1.z, w4.z, b4.z));
        float c3 = exp2f(fmaf(v1.w, w4.w, b4.w));

        float d0 = exp2f(fmaf(v2.x, w4.x, b4.x));
        float d1 = exp2f(fmaf(v2.y, w4.y, b4.y));
        float d2 = exp2f(fmaf(v2.z, w4.z, b4.z));
        float d3 = exp2f(fmaf(v2.w, w4.w, b4.w));

        float g0 = exp2f(fmaf(v3.x, w4.x, b4.x));
        float g1 = exp2f(fmaf(v3.y, w4.y, b4.y));
        float g2 = exp2f(fmaf(v3.z, w4.z, b4.z));
        float g3 = exp2f(fmaf(v3.w, w4.w, b4.w));

        float f0 = rsqrtf((1.0f + a0) * (1.0f + a1) * (1.0f + a2) * (1.0f + a3));
        float f1 = rsqrtf((1.0f + c0) * (1.0f + c1) * (1.0f + c2) * (1.0f + c3));
        float f2 = rsqrtf((1.0f + d0) * (1.0f + d1) * (1.0f + d2) * (1.0f + d3));
        float f3 = rsqrtf((1.0f + g0) * (1.0f + g1) * (1.0f + g2) * (1.0f + g3));

        // 4 interleaved multiply-reductions across each 16-lane half-warp
        #pragma unroll
        for (int off = 8; off > 0; off >>= 1) {
            f0 *= __shfl_xor_sync(0xFFFFFFFFu, f0, off, 16);
            f1 *= __shfl_xor_sync(0xFFFFFFFFu, f1, off, 16);
            f2 *= __shfl_xor_sync(0xFFFFFFFFu, f2, off, 16);
            f3 *= __shfl_xor_sync(0xFFFFFFFFu, f3, off, 16);
        }

        if (hlane == 0u) {
            // lanes 0/16 write rows {row0,+2,+4,+6} — 8 adjacent floats = 32B
            __stcs(out + row0,      f0);
            __stcs(out + row0 + 2u, f1);
            __stcs(out + row0 + 4u, f2);
            __stcs(out + row0 + 6u, f3);
        }
    }

    // Tail (n_rows not divisible by 8): leftover rows pair-wise.
    const unsigned tail_start = n_octs * 8u;
    if (tail_start < n_rows) {
        const unsigned n_pairs_tail = (n_rows - tail_start) >> 1;
        for (unsigned t = warp_id; t < n_pairs_tail; t += n_warps) {
            const unsigned row = tail_start + 2u * t + half;
            const float4 v = __ldcs(xv + row * 16u + hlane);
            float e0 = exp2f(fmaf(v.x, w4.x, b4.x));
            float e1 = exp2f(fmaf(v.y, w4.y, b4.y));
            float e2 = exp2f(fmaf(v.z, w4.z, b4.z));
            float e3 = exp2f(fmaf(v.w, w4.w, b4.w));
            float f = rsqrtf((1.0f + e0) * (1.0f + e1) * (1.0f + e2) * (1.0f + e3));
            #pragma unroll
            for (int off = 8; off > 0; off >>= 1)
                f *= __shfl_xor_sync(0xFFFFFFFFu, f, off, 16);
            if (hlane == 0u) out[row] = f;
        }
        if ((n_rows - tail_start) & 1u) {
            if (warp_id == 0u) {
                const unsigned row = n_rows - 1u;
                const float4 v = __ldcs(xv + row * 16u + hlane);
                float e0 = exp2f(fmaf(v.x, w4.x, b4.x));
                float e1 = exp2f(fmaf(v.y, w4.y, b4.y));
                float e2 = exp2f(fmaf(v.z, w4.z, b4.z));
                float e3 = exp2f(fmaf(v.w, w4.w, b4.w));
                float f = rsqrtf((1.0f + e0) * (1.0f + e1) * (1.0f + e2) * (1.0f + e3));
                #pragma unroll
                for (int off = 8; off > 0; off >>= 1)
                    f *= __shfl_xor_sync(0xFFFFFFFFu, f, off, 32);
                if (lane == 0u) out[row] = f;
            }
        }
    }
}

extern "C" void kernel_launch(void* const* d_in, const int* in_sizes, int n_in,
                              void* d_out, int out_size)
{
    const float* x = (const float*)d_in[0];   // [N, 64]
    const float* w = (const float*)d_in[1];   // [64]
    const float* b = (const float*)d_in[2];   // [64]
    float* out = (float*)d_out;               // [N]

    const unsigned n_rows = (unsigned)((long long)in_sizes[0] / 64);

    one_to_one_prod_kernel<<<GRID_BLOCKS, BLOCK_THREADS>>>(x, w, b, out, n_rows);
}